// round 11
// baseline (speedup 1.0000x reference)
#include <cuda_runtime.h>
#include <cuda_bf16.h>
#include <cstdint>
#include <math_constants.h>

// VectorQuantizer via mma.sync bf16 + exact fp32 rescue.
// R11: 2-pass emulation (x0e0 + x1e0 = x*e0; dropped codebook-lo pass entirely,
// err ~1e-5 std absorbed by MARGIN=2e-4), B1 tile removed, TILE_M 128->256
// (halves per-pixel B-fragment smem traffic). Ambiguous rows (top2 gap<=MARGIN)
// get whole-warp exact fp32 scans (numerics bit-matched reference in R1/R2).

#define VQ_K 512
#define VQ_D 64
#define VQ_HW 4096
#define TILE_M 256
#define NTILES 512
#define THREADS 512
#define MARGIN 2e-4f
#define XFS 264

// ---- shared memory layout (bytes) ----
#define SM_B0   0        // codebook hi bf16 [512 rows][128B]   64 KB
#define SM_A0   65536    // x tile hi bf16 [256 rows][128B]     32 KB
#define SM_A1   98304    // x tile lo bf16                      32 KB
#define SM_XF   131072   // x tile f32 [64][XFS]                67584 B
#define SM_ESQ  198656   // f32 e_sq[512]
#define SM_XSQ  200704   // f32 xsq[256]
#define SM_WIN  201728   // int winners[256]
#define SM_AMB  202752   // int ambiguous rows [256]
#define SM_CNT  203776   // int ambiguous count
#define SMEM_TOTAL 203840

// Rows are 128B (64 bf16) = 8 chunks of 16B; chunk at position chunk^(row&7)
// -> ldmatrix over 8 consecutive rows is bank-conflict-free.
__device__ __forceinline__ int swz(int row, int chunk) {
    return row * 128 + ((chunk ^ (row & 7)) << 4);
}
__device__ __forceinline__ uint32_t sptr(const void* p) {
    return (uint32_t)__cvta_generic_to_shared(p);
}
#define LDSM4(r0, r1, r2, r3, addr)                                            \
    asm volatile("ldmatrix.sync.aligned.m8n8.x4.shared.b16 {%0,%1,%2,%3}, [%4];" \
                 : "=r"(r0), "=r"(r1), "=r"(r2), "=r"(r3) : "r"(addr))

__device__ __forceinline__ void hmma(float& d0, float& d1, float& d2, float& d3,
                                     uint32_t a0, uint32_t a1, uint32_t a2, uint32_t a3,
                                     uint32_t b0, uint32_t b1) {
    asm volatile(
        "mma.sync.aligned.m16n8k16.row.col.f32.bf16.bf16.f32 "
        "{%0,%1,%2,%3}, {%4,%5,%6,%7}, {%8,%9}, {%0,%1,%2,%3};"
        : "+f"(d0), "+f"(d1), "+f"(d2), "+f"(d3)
        : "r"(a0), "r"(a1), "r"(a2), "r"(a3), "r"(b0), "r"(b1));
}

__device__ __forceinline__ uint32_t pack2bf(float a, float b) {
    __nv_bfloat162 h = __floats2bfloat162_rn(a, b);
    return *reinterpret_cast<uint32_t*>(&h);
}
__device__ __forceinline__ float bf_hi(float v) {
    return __bfloat162float(__float2bfloat16(v));
}

// Exact fp32 distance, numerics identical to round-1 (bit-matched reference):
// sequential FMA dot, dist = fl(fl(xsq+esq) + (-2*dot)).
__device__ __forceinline__ float exact_dist(const float* __restrict__ xf,
                                            const float* __restrict__ emb,
                                            float xsq, float esqk, int k, int p) {
    const float4* er = reinterpret_cast<const float4*>(emb + (size_t)k * VQ_D);
    float dot = 0.0f;
    #pragma unroll
    for (int q = 0; q < 16; q++) {
        const float4 f = __ldg(er + q);
        dot = __fmaf_rn(xf[(4 * q + 0) * XFS + p], f.x, dot);
        dot = __fmaf_rn(xf[(4 * q + 1) * XFS + p], f.y, dot);
        dot = __fmaf_rn(xf[(4 * q + 2) * XFS + p], f.z, dot);
        dot = __fmaf_rn(xf[(4 * q + 3) * XFS + p], f.w, dot);
    }
    return __fadd_rn(__fadd_rn(xsq, esqk), __fmul_rn(-2.0f, dot));
}

__global__ __launch_bounds__(THREADS, 1)
void vq_hmma_kernel(const float* __restrict__ x,
                    const float* __restrict__ emb,
                    float* __restrict__ out) {
    extern __shared__ char sm[];
    float* xf      = reinterpret_cast<float*>(sm + SM_XF);
    float* esq     = reinterpret_cast<float*>(sm + SM_ESQ);
    float* xsqs    = reinterpret_cast<float*>(sm + SM_XSQ);
    int*   winners = reinterpret_cast<int*>(sm + SM_WIN);
    int*   amb     = reinterpret_cast<int*>(sm + SM_AMB);
    int*   ambcnt  = reinterpret_cast<int*>(sm + SM_CNT);

    const int tid  = threadIdx.x;
    const int wid  = tid >> 5;       // 0..15, warp covers rows [wid*16, wid*16+16)
    const int lane = tid & 31;
    const int g    = lane & 3;
    const int qr   = lane >> 2;

    // ---- prologue: stage codebook hi (swizzled chunks) + exact e_sq ----
    #pragma unroll 4
    for (int it = 0; it < 16; it++) {
        const int lin = it * THREADS + tid;          // 8192 float4s
        const int k = lin >> 4, q = lin & 15;
        const float4 f = __ldg(reinterpret_cast<const float4*>(emb + k * VQ_D) + q);
        const int off = swz(k, q >> 1) + (q & 1) * 8;
        *reinterpret_cast<uint2*>(sm + SM_B0 + off) =
            make_uint2(pack2bf(f.x, f.y), pack2bf(f.z, f.w));
    }
    {
        const int k = tid;                           // THREADS == VQ_K
        const float4* er = reinterpret_cast<const float4*>(emb + k * VQ_D);
        float s = 0.0f;
        #pragma unroll
        for (int q = 0; q < 16; q++) {
            const float4 f = __ldg(er + q);
            s = __fadd_rn(s, __fmul_rn(f.x, f.x));
            s = __fadd_rn(s, __fmul_rn(f.y, f.y));
            s = __fadd_rn(s, __fmul_rn(f.z, f.z));
            s = __fadd_rn(s, __fmul_rn(f.w, f.w));
        }
        esq[k] = s;
    }
    __syncthreads();

    for (int tile = blockIdx.x; tile < NTILES; tile += gridDim.x) {
        const int pix0 = tile * TILE_M;
        const int bIdx = pix0 >> 12;
        const int hw0  = pix0 & 4095;
        const float* xbase = x + (size_t)bIdx * VQ_D * VQ_HW + hw0;
        float* obase = out + (size_t)bIdx * VQ_D * VQ_HW + hw0;

        // ---- pass 1: coalesced x load -> xf (f32, channel-major) ----
        #pragma unroll
        for (int it = 0; it < 8; it++) {
            const int lin = it * THREADS + tid;      // 4096 float4s
            const int c = lin >> 6, q = lin & 63, p = q * 4;
            const float4 f = __ldg(reinterpret_cast<const float4*>(
                xbase + (size_t)c * VQ_HW + p));
            *reinterpret_cast<float4*>(xf + c * XFS + p) = f;
        }
        if (tid == 0) *ambcnt = 0;
        __syncthreads();

        // ---- pass 2: transpose xf -> bf16 hi/lo A tiles ----
        #pragma unroll
        for (int i = 0; i < 4; i++) {
            const int task = i * THREADS + tid;      // 2048 = 256 rows x 8 chunks
            const int p = task & 255, h = task >> 8;
            float v[8];
            #pragma unroll
            for (int j = 0; j < 8; j++) v[j] = xf[(8 * h + j) * XFS + p];
            const int off = swz(p, h);
            *reinterpret_cast<uint4*>(sm + SM_A0 + off) =
                make_uint4(pack2bf(v[0], v[1]), pack2bf(v[2], v[3]),
                           pack2bf(v[4], v[5]), pack2bf(v[6], v[7]));
            *reinterpret_cast<uint4*>(sm + SM_A1 + off) =
                make_uint4(pack2bf(v[0] - bf_hi(v[0]), v[1] - bf_hi(v[1])),
                           pack2bf(v[2] - bf_hi(v[2]), v[3] - bf_hi(v[3])),
                           pack2bf(v[4] - bf_hi(v[4]), v[5] - bf_hi(v[5])),
                           pack2bf(v[6] - bf_hi(v[6]), v[7] - bf_hi(v[7])));
        }
        if (tid < TILE_M) {
            float s = 0.0f;
            #pragma unroll
            for (int c = 0; c < VQ_D; c++) {
                const float v = xf[c * XFS + tid];
                s = __fadd_rn(s, __fmul_rn(v, v));
            }
            xsqs[tid] = s;
        }
        __syncthreads();

        // ---- A fragments via ldmatrix.x4 (conflict-free) ----
        const int arow = wid * 16 + (lane & 7) + ((lane >> 3) & 1) * 8;
        uint32_t aHi[4][4], aLo[4][4];
        #pragma unroll
        for (int ks = 0; ks < 4; ks++) {
            const int ach = 2 * ks + (lane >> 4);
            LDSM4(aHi[ks][0], aHi[ks][1], aHi[ks][2], aHi[ks][3],
                  sptr(sm + SM_A0 + swz(arow, ach)));
            LDSM4(aLo[ks][0], aLo[ks][1], aLo[ks][2], aLo[ks][3],
                  sptr(sm + SM_A1 + swz(arow, ach)));
        }

        // branchless top-2 state per row (r0, r1)
        float m1[2] = {CUDART_INF_F, CUDART_INF_F};
        float m2[2] = {CUDART_INF_F, CUDART_INF_F};
        int   ki[2] = {0x7FFFFFFF, 0x7FFFFFFF};

        #define UPD(rr, s, kk) {                                   \
            const bool lt = (s) < m1[rr];                          \
            m2[rr] = fminf(m2[rr], lt ? m1[rr] : (s));             \
            ki[rr] = lt ? (kk) : ki[rr];                           \
            m1[rr] = lt ? (s) : m1[rr]; }

        const int browo = (lane & 7) + (lane >> 4) * 8;
        const int bchs  = (lane >> 3) & 1;

        for (int nc = 0; nc < 8; nc++) {      // 8 chunks of 64 codes
            float acc[8][4];
            #pragma unroll
            for (int nf = 0; nf < 8; nf++) {
                acc[nf][0] = 0.f; acc[nf][1] = 0.f; acc[nf][2] = 0.f; acc[nf][3] = 0.f;
            }
            #pragma unroll
            for (int ks = 0; ks < 4; ks++) {
                uint32_t bh[8][2];
                #pragma unroll
                for (int pr = 0; pr < 4; pr++) {
                    const int row = nc * 64 + pr * 16 + browo;
                    const int ch  = 2 * ks + bchs;
                    LDSM4(bh[2 * pr][0], bh[2 * pr][1],
                          bh[2 * pr + 1][0], bh[2 * pr + 1][1],
                          sptr(sm + SM_B0 + swz(row, ch)));
                }
                #pragma unroll
                for (int nf = 0; nf < 8; nf++)   // x0*e0
                    hmma(acc[nf][0], acc[nf][1], acc[nf][2], acc[nf][3],
                         aHi[ks][0], aHi[ks][1], aHi[ks][2], aHi[ks][3],
                         bh[nf][0], bh[nf][1]);
                #pragma unroll
                for (int nf = 0; nf < 8; nf++)   // x1*e0
                    hmma(acc[nf][0], acc[nf][1], acc[nf][2], acc[nf][3],
                         aLo[ks][0], aLo[ks][1], aLo[ks][2], aLo[ks][3],
                         bh[nf][0], bh[nf][1]);
            }
            // scores: rank = esq - 2*dot (xsq constant per row)
            #pragma unroll
            for (int nf = 0; nf < 8; nf++) {
                const int col = nc * 64 + nf * 8 + 2 * g;
                const float2 eq = *reinterpret_cast<const float2*>(esq + col);
                float s;
                s = __fmaf_rn(-2.0f, acc[nf][0], eq.x); UPD(0, s, col);
                s = __fmaf_rn(-2.0f, acc[nf][1], eq.y); UPD(0, s, col + 1);
                s = __fmaf_rn(-2.0f, acc[nf][2], eq.x); UPD(1, s, col);
                s = __fmaf_rn(-2.0f, acc[nf][3], eq.y); UPD(1, s, col + 1);
            }
        }
        #undef UPD

        // ---- quad reduce (fully converged); fast path or enqueue ambiguous ----
        #pragma unroll
        for (int rr = 0; rr < 2; rr++) {
            #pragma unroll
            for (int d = 1; d <= 2; d <<= 1) {
                const float o1 = __shfl_xor_sync(0xffffffffu, m1[rr], d);
                const float o2 = __shfl_xor_sync(0xffffffffu, m2[rr], d);
                const int   oi = __shfl_xor_sync(0xffffffffu, ki[rr], d);
                const bool take = (o1 < m1[rr]) || (o1 == m1[rr] && oi < ki[rr]);
                m2[rr] = fminf(fminf(m2[rr], o2), take ? m1[rr] : o1);
                ki[rr] = take ? oi : ki[rr];
                m1[rr] = take ? o1 : m1[rr];
            }
            if (g == 0) {
                const int row = wid * 16 + qr + rr * 8;
                if (m2[rr] - m1[rr] > MARGIN) {
                    winners[row] = ki[rr];
                } else {
                    const int pos = atomicAdd(ambcnt, 1);
                    amb[pos] = row;
                }
            }
        }
        __syncthreads();

        // ---- cooperative exact rescue: one warp per ambiguous row ----
        {
            const int namb = *ambcnt;
            for (int i = wid; i < namb; i += 16) {
                const int row = amb[i];
                const float xq = xsqs[row];
                float bd = CUDART_INF_F; int bk = 0x7FFFFFFF;
                #pragma unroll 4
                for (int k = lane; k < VQ_K; k += 32) {
                    const float d = exact_dist(xf, emb, xq, esq[k], k, row);
                    if (d < bd || (d == bd && k < bk)) { bd = d; bk = k; }
                }
                #pragma unroll
                for (int off = 16; off; off >>= 1) {
                    const float od = __shfl_xor_sync(0xffffffffu, bd, off);
                    const int   oi = __shfl_xor_sync(0xffffffffu, bk, off);
                    if (od < bd || (od == bd && oi < bk)) { bd = od; bk = oi; }
                }
                if (lane == 0) winners[row] = bk;
            }
        }
        __syncthreads();

        // ---- gather winner rows (coalesced) into xf, then coalesced stores ----
        #pragma unroll
        for (int it = 0; it < 8; it++) {
            const int lin = it * THREADS + tid;   // 4096: 256 pixels x 16 quads
            const int p = lin >> 4, q = lin & 15;
            const float4 f = __ldg(reinterpret_cast<const float4*>(
                emb + (size_t)winners[p] * VQ_D) + q);
            const int c = q * 4;
            xf[(c + 0) * XFS + p] = f.x;
            xf[(c + 1) * XFS + p] = f.y;
            xf[(c + 2) * XFS + p] = f.z;
            xf[(c + 3) * XFS + p] = f.w;
        }
        __syncthreads();
        #pragma unroll
        for (int it = 0; it < 8; it++) {
            const int lin = it * THREADS + tid;
            const int c = lin >> 6, q = lin & 63, p = q * 4;
            const float4 v = *reinterpret_cast<const float4*>(xf + c * XFS + p);
            *reinterpret_cast<float4*>(obase + (size_t)c * VQ_HW + p) = v;
        }
        __syncthreads();   // protect smem for next tile's staging
    }
}

extern "C" void kernel_launch(void* const* d_in, const int* in_sizes, int n_in,
                              void* d_out, int out_size) {
    (void)in_sizes; (void)n_in; (void)out_size;
    const float* x   = (const float*)d_in[0];
    const float* emb = (const float*)d_in[1];
    float* out = (float*)d_out;

    cudaFuncSetAttribute(vq_hmma_kernel, cudaFuncAttributeMaxDynamicSharedMemorySize,
                         SMEM_TOTAL);

    vq_hmma_kernel<<<152, THREADS, SMEM_TOTAL>>>(x, emb, out);
}

// round 12
// speedup vs baseline: 1.4877x; 1.4877x over previous
#include <cuda_runtime.h>
#include <cuda_fp16.h>
#include <cstdint>
#include <math_constants.h>

// VectorQuantizer via single-pass fp16 mma.sync + exact fp32 rescue.
// R12 = R10 skeleton (180.7us, rel_err 0) with the 3-pass bf16 emulation
// replaced by ONE fp16 pass: fp16's 11-bit mantissa on |e|<=0.002, x~N(0,1)
// gives score error ~4e-6 std; MARGIN 6e-5 is ~30 sigma. Ambiguous rows
// (top2 gap <= MARGIN) get whole-warp exact fp32 scans (bit-matched reference).

#define VQ_K 512
#define VQ_D 64
#define VQ_HW 4096
#define TILE_M 128
#define NTILES 1024
#define THREADS 512
#define MARGIN 6e-5f
#define XFS 132

// ---- shared memory layout (bytes) ----
#define SM_B0   0        // codebook fp16 [512 rows][128B]      64 KB
#define SM_A0   65536    // x tile fp16 [128 rows][128B]        16 KB
#define SM_XF   81920    // x tile f32 [64][XFS]                33792 B
#define SM_ESQ  115712   // f32 e_sq[512]
#define SM_XSQ  117760   // f32 xsq[128]
#define SM_WIN  118272   // int winners[128]
#define SM_HM1  118784   // f32 half-min1 [2][128]
#define SM_HM2  119808   // f32 half-min2 [2][128]
#define SM_HIX  120832   // int half-idx  [2][128]
#define SM_AMB  121856   // int ambiguous rows [128]
#define SM_CNT  122368   // int ambiguous count
#define SMEM_TOTAL 122400

// Rows are 128B (64 fp16) = 8 chunks of 16B; chunk at position chunk^(row&7)
// -> ldmatrix over 8 consecutive rows is bank-conflict-free.
__device__ __forceinline__ int swz(int row, int chunk) {
    return row * 128 + ((chunk ^ (row & 7)) << 4);
}
__device__ __forceinline__ uint32_t sptr(const void* p) {
    return (uint32_t)__cvta_generic_to_shared(p);
}
#define LDSM4(r0, r1, r2, r3, addr)                                            \
    asm volatile("ldmatrix.sync.aligned.m8n8.x4.shared.b16 {%0,%1,%2,%3}, [%4];" \
                 : "=r"(r0), "=r"(r1), "=r"(r2), "=r"(r3) : "r"(addr))

__device__ __forceinline__ void hmma(float& d0, float& d1, float& d2, float& d3,
                                     uint32_t a0, uint32_t a1, uint32_t a2, uint32_t a3,
                                     uint32_t b0, uint32_t b1) {
    asm volatile(
        "mma.sync.aligned.m16n8k16.row.col.f32.f16.f16.f32 "
        "{%0,%1,%2,%3}, {%4,%5,%6,%7}, {%8,%9}, {%0,%1,%2,%3};"
        : "+f"(d0), "+f"(d1), "+f"(d2), "+f"(d3)
        : "r"(a0), "r"(a1), "r"(a2), "r"(a3), "r"(b0), "r"(b1));
}

__device__ __forceinline__ uint32_t pack2h(float a, float b) {
    __half2 h = __floats2half2_rn(a, b);
    return *reinterpret_cast<uint32_t*>(&h);
}

// Exact fp32 distance, numerics identical to round-1 (bit-matched reference):
// sequential FMA dot, dist = fl(fl(xsq+esq) + (-2*dot)).
__device__ __forceinline__ float exact_dist(const float* __restrict__ xf,
                                            const float* __restrict__ emb,
                                            float xsq, float esqk, int k, int p) {
    const float4* er = reinterpret_cast<const float4*>(emb + (size_t)k * VQ_D);
    float dot = 0.0f;
    #pragma unroll
    for (int q = 0; q < 16; q++) {
        const float4 f = __ldg(er + q);
        dot = __fmaf_rn(xf[(4 * q + 0) * XFS + p], f.x, dot);
        dot = __fmaf_rn(xf[(4 * q + 1) * XFS + p], f.y, dot);
        dot = __fmaf_rn(xf[(4 * q + 2) * XFS + p], f.z, dot);
        dot = __fmaf_rn(xf[(4 * q + 3) * XFS + p], f.w, dot);
    }
    return __fadd_rn(__fadd_rn(xsq, esqk), __fmul_rn(-2.0f, dot));
}

__global__ __launch_bounds__(THREADS, 1)
void vq_hmma_kernel(const float* __restrict__ x,
                    const float* __restrict__ emb,
                    float* __restrict__ out) {
    extern __shared__ char sm[];
    float* xf      = reinterpret_cast<float*>(sm + SM_XF);
    float* esq     = reinterpret_cast<float*>(sm + SM_ESQ);
    float* xsqs    = reinterpret_cast<float*>(sm + SM_XSQ);
    int*   winners = reinterpret_cast<int*>(sm + SM_WIN);
    float* hm1     = reinterpret_cast<float*>(sm + SM_HM1);
    float* hm2     = reinterpret_cast<float*>(sm + SM_HM2);
    int*   hix     = reinterpret_cast<int*>(sm + SM_HIX);
    int*   amb     = reinterpret_cast<int*>(sm + SM_AMB);
    int*   ambcnt  = reinterpret_cast<int*>(sm + SM_CNT);

    const int tid  = threadIdx.x;
    const int wid  = tid >> 5;
    const int lane = tid & 31;
    const int g    = lane & 3;
    const int qr   = lane >> 2;
    const int hid  = wid >> 3;       // code half: 0 -> k<256, 1 -> k>=256
    const int wrow = wid & 7;        // row block

    // ---- prologue: stage codebook fp16 (swizzled chunks) + exact e_sq ----
    #pragma unroll 4
    for (int it = 0; it < 16; it++) {
        const int lin = it * THREADS + tid;          // 8192 float4s
        const int k = lin >> 4, q = lin & 15;
        const float4 f = __ldg(reinterpret_cast<const float4*>(emb + k * VQ_D) + q);
        const int off = swz(k, q >> 1) + (q & 1) * 8;
        *reinterpret_cast<uint2*>(sm + SM_B0 + off) =
            make_uint2(pack2h(f.x, f.y), pack2h(f.z, f.w));
    }
    {
        const int k = tid;                           // THREADS == VQ_K
        const float4* er = reinterpret_cast<const float4*>(emb + k * VQ_D);
        float s = 0.0f;
        #pragma unroll
        for (int q = 0; q < 16; q++) {
            const float4 f = __ldg(er + q);
            s = __fadd_rn(s, __fmul_rn(f.x, f.x));
            s = __fadd_rn(s, __fmul_rn(f.y, f.y));
            s = __fadd_rn(s, __fmul_rn(f.z, f.z));
            s = __fadd_rn(s, __fmul_rn(f.w, f.w));
        }
        esq[k] = s;
    }
    __syncthreads();

    for (int tile = blockIdx.x; tile < NTILES; tile += gridDim.x) {
        const int pix0 = tile * TILE_M;
        const int bIdx = pix0 >> 12;
        const int hw0  = pix0 & 4095;
        const float* xbase = x + (size_t)bIdx * VQ_D * VQ_HW + hw0;
        float* obase = out + (size_t)bIdx * VQ_D * VQ_HW + hw0;

        // ---- pass 1: coalesced x load -> xf (f32, channel-major) ----
        #pragma unroll
        for (int it = 0; it < 4; it++) {
            const int lin = it * THREADS + tid;      // 2048 float4s
            const int c = lin >> 5, q = lin & 31, p = q * 4;
            const float4 f = __ldg(reinterpret_cast<const float4*>(
                xbase + (size_t)c * VQ_HW + p));
            *reinterpret_cast<float4*>(xf + c * XFS + p) = f;
        }
        if (tid == 0) *ambcnt = 0;
        __syncthreads();

        // ---- pass 2: transpose xf -> fp16 A tile ----
        #pragma unroll
        for (int i = 0; i < 2; i++) {
            const int task = i * THREADS + tid;      // 1024 = 128 rows x 8 chunks
            const int p = task & 127, h = task >> 7;
            float v[8];
            #pragma unroll
            for (int j = 0; j < 8; j++) v[j] = xf[(8 * h + j) * XFS + p];
            const int off = swz(p, h);
            *reinterpret_cast<uint4*>(sm + SM_A0 + off) =
                make_uint4(pack2h(v[0], v[1]), pack2h(v[2], v[3]),
                           pack2h(v[4], v[5]), pack2h(v[6], v[7]));
        }
        if (tid < TILE_M) {
            float s = 0.0f;
            #pragma unroll
            for (int c = 0; c < VQ_D; c++) {
                const float v = xf[c * XFS + tid];
                s = __fadd_rn(s, __fmul_rn(v, v));
            }
            xsqs[tid] = s;
        }
        __syncthreads();

        // ---- A fragments via ldmatrix.x4 (conflict-free) ----
        const int arow = wrow * 16 + (lane & 7) + ((lane >> 3) & 1) * 8;
        uint32_t aF[4][4];
        #pragma unroll
        for (int ks = 0; ks < 4; ks++) {
            const int ach = 2 * ks + (lane >> 4);
            LDSM4(aF[ks][0], aF[ks][1], aF[ks][2], aF[ks][3],
                  sptr(sm + SM_A0 + swz(arow, ach)));
        }

        // branchless top-2 state per row (r0, r1)
        float m1[2] = {CUDART_INF_F, CUDART_INF_F};
        float m2[2] = {CUDART_INF_F, CUDART_INF_F};
        int   ki[2] = {0x7FFFFFFF, 0x7FFFFFFF};

        #define UPD(rr, s, kk) {                                   \
            const bool lt = (s) < m1[rr];                          \
            m2[rr] = fminf(m2[rr], lt ? m1[rr] : (s));             \
            ki[rr] = lt ? (kk) : ki[rr];                           \
            m1[rr] = lt ? (s) : m1[rr]; }

        const int browo = (lane & 7) + (lane >> 4) * 8;
        const int bchs  = (lane >> 3) & 1;

        for (int nc = 0; nc < 4; nc++) {      // 4 chunks of 64 codes (this half)
            float acc[8][4];
            #pragma unroll
            for (int nf = 0; nf < 8; nf++) {
                acc[nf][0] = 0.f; acc[nf][1] = 0.f; acc[nf][2] = 0.f; acc[nf][3] = 0.f;
            }
            #pragma unroll
            for (int ks = 0; ks < 4; ks++) {
                uint32_t bh[8][2];
                #pragma unroll
                for (int pr = 0; pr < 4; pr++) {
                    const int row = hid * 256 + nc * 64 + pr * 16 + browo;
                    const int ch  = 2 * ks + bchs;
                    LDSM4(bh[2 * pr][0], bh[2 * pr][1],
                          bh[2 * pr + 1][0], bh[2 * pr + 1][1],
                          sptr(sm + SM_B0 + swz(row, ch)));
                }
                #pragma unroll
                for (int nf = 0; nf < 8; nf++)
                    hmma(acc[nf][0], acc[nf][1], acc[nf][2], acc[nf][3],
                         aF[ks][0], aF[ks][1], aF[ks][2], aF[ks][3],
                         bh[nf][0], bh[nf][1]);
            }
            // scores: rank = esq - 2*dot (xsq constant per row)
            #pragma unroll
            for (int nf = 0; nf < 8; nf++) {
                const int col = hid * 256 + nc * 64 + nf * 8 + 2 * g;
                const float2 eq = *reinterpret_cast<const float2*>(esq + col);
                float s;
                s = __fmaf_rn(-2.0f, acc[nf][0], eq.x); UPD(0, s, col);
                s = __fmaf_rn(-2.0f, acc[nf][1], eq.y); UPD(0, s, col + 1);
                s = __fmaf_rn(-2.0f, acc[nf][2], eq.x); UPD(1, s, col);
                s = __fmaf_rn(-2.0f, acc[nf][3], eq.y); UPD(1, s, col + 1);
            }
        }
        #undef UPD

        // ---- quad reduce (fully converged; no divergence hazards) ----
        #pragma unroll
        for (int rr = 0; rr < 2; rr++) {
            #pragma unroll
            for (int d = 1; d <= 2; d <<= 1) {
                const float o1 = __shfl_xor_sync(0xffffffffu, m1[rr], d);
                const float o2 = __shfl_xor_sync(0xffffffffu, m2[rr], d);
                const int   oi = __shfl_xor_sync(0xffffffffu, ki[rr], d);
                const bool take = (o1 < m1[rr]) || (o1 == m1[rr] && oi < ki[rr]);
                m2[rr] = fminf(fminf(m2[rr], o2), take ? m1[rr] : o1);
                ki[rr] = take ? oi : ki[rr];
                m1[rr] = take ? o1 : m1[rr];
            }
            if (g == 0) {
                const int row = wrow * 16 + qr + rr * 8;
                hm1[hid * 128 + row] = m1[rr];
                hm2[hid * 128 + row] = m2[rr];
                hix[hid * 128 + row] = ki[rr];
            }
        }
        __syncthreads();

        // ---- combine halves; fast path or enqueue ambiguous ----
        if (tid < TILE_M) {
            const int row = tid;
            const float a1 = hm1[row],       a2 = hm2[row];
            const float b1 = hm1[128 + row], b2 = hm2[128 + row];
            const int   ai = hix[row],       bi = hix[128 + row];
            const bool take = (b1 < a1) || (b1 == a1 && bi < ai);
            const float M1 = take ? b1 : a1;
            const int   IX = take ? bi : ai;
            const float M2 = fminf(fminf(a2, b2), take ? a1 : b1);
            if (M2 - M1 > MARGIN) {
                winners[row] = IX;
            } else {
                const int pos = atomicAdd(ambcnt, 1);
                amb[pos] = row;
            }
        }
        __syncthreads();

        // ---- cooperative exact rescue: one warp per ambiguous row ----
        {
            const int namb = *ambcnt;
            for (int i = wid; i < namb; i += 16) {
                const int row = amb[i];
                const float xq = xsqs[row];
                float bd = CUDART_INF_F; int bk = 0x7FFFFFFF;
                #pragma unroll 4
                for (int k = lane; k < VQ_K; k += 32) {
                    const float d = exact_dist(xf, emb, xq, esq[k], k, row);
                    if (d < bd || (d == bd && k < bk)) { bd = d; bk = k; }
                }
                #pragma unroll
                for (int off = 16; off; off >>= 1) {
                    const float od = __shfl_xor_sync(0xffffffffu, bd, off);
                    const int   oi = __shfl_xor_sync(0xffffffffu, bk, off);
                    if (od < bd || (od == bd && oi < bk)) { bd = od; bk = oi; }
                }
                if (lane == 0) winners[row] = bk;
            }
        }
        __syncthreads();

        // ---- gather winner rows (coalesced) into xf, then coalesced stores ----
        #pragma unroll
        for (int it = 0; it < 4; it++) {
            const int lin = it * THREADS + tid;   // 2048: 128 pixels x 16 quads
            const int p = lin >> 4, q = lin & 15;
            const float4 f = __ldg(reinterpret_cast<const float4*>(
                emb + (size_t)winners[p] * VQ_D) + q);
            const int c = q * 4;
            xf[(c + 0) * XFS + p] = f.x;
            xf[(c + 1) * XFS + p] = f.y;
            xf[(c + 2) * XFS + p] = f.z;
            xf[(c + 3) * XFS + p] = f.w;
        }
        __syncthreads();
        #pragma unroll
        for (int it = 0; it < 4; it++) {
            const int lin = it * THREADS + tid;
            const int c = lin >> 5, q = lin & 31, p = q * 4;
            const float4 v = *reinterpret_cast<const float4*>(xf + c * XFS + p);
            *reinterpret_cast<float4*>(obase + (size_t)c * VQ_HW + p) = v;
        }
        __syncthreads();   // protect smem for next tile's staging
    }
}

extern "C" void kernel_launch(void* const* d_in, const int* in_sizes, int n_in,
                              void* d_out, int out_size) {
    (void)in_sizes; (void)n_in; (void)out_size;
    const float* x   = (const float*)d_in[0];
    const float* emb = (const float*)d_in[1];
    float* out = (float*)d_out;

    cudaFuncSetAttribute(vq_hmma_kernel, cudaFuncAttributeMaxDynamicSharedMemorySize,
                         SMEM_TOTAL);

    vq_hmma_kernel<<<152, THREADS, SMEM_TOTAL>>>(x, emb, out);
}

// round 13
// speedup vs baseline: 2.6392x; 1.7741x over previous
#include <cuda_runtime.h>
#include <cuda_fp16.h>
#include <cstdint>
#include <math_constants.h>

// VectorQuantizer, barrier-free warp-autonomous version.
// Each warp owns 16 pixels end-to-end: stage x -> private smem A slice ->
// m16 x n512 x k64 fp16 mma.sync vs shared codebook -> in-warp top-2 ->
// in-warp exact fp32 rescue (gap <= MARGIN) -> gather + store.
// No __syncthreads in the main loop (R12's 6-barrier phase structure was the
// bottleneck: all pipes <12% busy). fp16 1-pass + MARGIN 6e-5 validated in R12
// (rel_err 0.0). Exact fp32 formula bit-matched the reference in R1/R2.

#define VQ_K 512
#define VQ_D 64
#define VQ_HW 4096
#define NWTILES 8192         // 131072 px / 16 px per warp-tile
#define THREADS 512
#define NWARPS 16
#define GRID 304             // 2 CTAs/SM if smem permits; graceful otherwise
#define MARGIN 6e-5f

// ---- shared memory layout (bytes) ----
#define SM_B0   0                       // codebook fp16 [512][128B]  64 KB
#define SM_ESQ  65536                   // f32 e_sq[512]               2 KB
#define SM_A    67584                   // per-warp A slices: 16 x 2048
#define SM_SCR  100352                  // per-warp scratch: 16 x 384
#define SMEM_TOTAL 106496
// scratch per warp: f32 xrow[64] (256B) + int win[16] (64B) + pad

__device__ __forceinline__ int swz(int row, int chunk) {
    return row * 128 + ((chunk ^ (row & 7)) << 4);
}
__device__ __forceinline__ uint32_t sptr(const void* p) {
    return (uint32_t)__cvta_generic_to_shared(p);
}
#define LDSM4(r0, r1, r2, r3, addr)                                            \
    asm volatile("ldmatrix.sync.aligned.m8n8.x4.shared.b16 {%0,%1,%2,%3}, [%4];" \
                 : "=r"(r0), "=r"(r1), "=r"(r2), "=r"(r3) : "r"(addr))

__device__ __forceinline__ void hmma(float& d0, float& d1, float& d2, float& d3,
                                     uint32_t a0, uint32_t a1, uint32_t a2, uint32_t a3,
                                     uint32_t b0, uint32_t b1) {
    asm volatile(
        "mma.sync.aligned.m16n8k16.row.col.f32.f16.f16.f32 "
        "{%0,%1,%2,%3}, {%4,%5,%6,%7}, {%8,%9}, {%0,%1,%2,%3};"
        : "+f"(d0), "+f"(d1), "+f"(d2), "+f"(d3)
        : "r"(a0), "r"(a1), "r"(a2), "r"(a3), "r"(b0), "r"(b1));
}

__device__ __forceinline__ uint32_t pack2h(float a, float b) {
    __half2 h = __floats2half2_rn(a, b);
    return *reinterpret_cast<uint32_t*>(&h);
}

// Exact fp32 distance, numerics identical to round-1 (bit-matched reference):
// sequential FMA dot over channels, dist = fl(fl(xsq+esq) + (-2*dot)).
__device__ __forceinline__ float exact_dist(const float* __restrict__ xrow,
                                            const float* __restrict__ emb,
                                            float xsq, float esqk, int k) {
    const float4* er = reinterpret_cast<const float4*>(emb + (size_t)k * VQ_D);
    float dot = 0.0f;
    #pragma unroll
    for (int q = 0; q < 16; q++) {
        const float4 f = __ldg(er + q);
        dot = __fmaf_rn(xrow[4 * q + 0], f.x, dot);
        dot = __fmaf_rn(xrow[4 * q + 1], f.y, dot);
        dot = __fmaf_rn(xrow[4 * q + 2], f.z, dot);
        dot = __fmaf_rn(xrow[4 * q + 3], f.w, dot);
    }
    return __fadd_rn(__fadd_rn(xsq, esqk), __fmul_rn(-2.0f, dot));
}

__global__ __launch_bounds__(THREADS, 1)
void vq_hmma_kernel(const float* __restrict__ x,
                    const float* __restrict__ emb,
                    float* __restrict__ out) {
    extern __shared__ char sm[];
    float* esq = reinterpret_cast<float*>(sm + SM_ESQ);

    const int tid  = threadIdx.x;
    const int wid  = tid >> 5;
    const int lane = tid & 31;
    const int g    = lane & 3;
    const int qr   = lane >> 2;

    char*  aslice = sm + SM_A + wid * 2048;
    float* scrX   = reinterpret_cast<float*>(sm + SM_SCR + wid * 384);
    int*   scrWin = reinterpret_cast<int*>(sm + SM_SCR + wid * 384 + 256);

    // ---- prologue: stage codebook fp16 (swizzled) + exact e_sq ----
    #pragma unroll 4
    for (int it = 0; it < 16; it++) {
        const int lin = it * THREADS + tid;          // 8192 float4s
        const int k = lin >> 4, q = lin & 15;
        const float4 f = __ldg(reinterpret_cast<const float4*>(emb + k * VQ_D) + q);
        const int off = swz(k, q >> 1) + (q & 1) * 8;
        *reinterpret_cast<uint2*>(sm + SM_B0 + off) =
            make_uint2(pack2h(f.x, f.y), pack2h(f.z, f.w));
    }
    {
        const int k = tid;                           // THREADS == VQ_K
        const float4* er = reinterpret_cast<const float4*>(emb + k * VQ_D);
        float s = 0.0f;
        #pragma unroll
        for (int q = 0; q < 16; q++) {
            const float4 f = __ldg(er + q);
            s = __fadd_rn(s, __fmul_rn(f.x, f.x));
            s = __fadd_rn(s, __fmul_rn(f.y, f.y));
            s = __fadd_rn(s, __fmul_rn(f.z, f.z));
            s = __fadd_rn(s, __fmul_rn(f.w, f.w));
        }
        esq[k] = s;
    }
    __syncthreads();   // only block barrier in the kernel

    const int gwarp   = blockIdx.x * NWARPS + wid;
    const int gstride = gridDim.x * NWARPS;

    const int browo = (lane & 7) + (lane >> 4) * 8;
    const int bchs  = (lane >> 3) & 1;
    const int arowL = (lane & 7) + ((lane >> 3) & 1) * 8;

    for (int wt = gwarp; wt < NWTILES; wt += gstride) {
        const int p0 = wt * 16;
        const int b  = p0 >> 12;
        const int hw = p0 & 4095;
        const float* xb = x + (size_t)b * VQ_D * VQ_HW + hw;
        float* ob = out + (size_t)b * VQ_D * VQ_HW + hw;

        __syncwarp();   // previous tile's LDSM fully done before slice rewrite

        // ---- stage this warp's 16 x-rows into its fp16 A slice ----
        // iter j: lanes 0-15 load channel 2j+? ... lane l: c=2j+(l>>4), p=l&15.
        #pragma unroll
        for (int h = 0; h < 8; h++) {
            uint32_t pr[4];
            #pragma unroll
            for (int jj = 0; jj < 4; jj++) {
                const int j = 4 * h + jj;
                const int c = 2 * j + (lane >> 4);
                const int p = lane & 15;
                const float v = __ldg(xb + (size_t)c * VQ_HW + p);
                const float o = __shfl_xor_sync(0xffffffffu, v, 16);
                pr[jj] = pack2h(v, o);               // valid on lanes < 16
            }
            if (lane < 16) {
                *reinterpret_cast<uint4*>(aslice + swz(lane, h)) =
                    make_uint4(pr[0], pr[1], pr[2], pr[3]);
            }
        }
        __syncwarp();

        // ---- A fragments via ldmatrix.x4 ----
        uint32_t aF[4][4];
        #pragma unroll
        for (int ks = 0; ks < 4; ks++) {
            const int ach = 2 * ks + (lane >> 4);
            LDSM4(aF[ks][0], aF[ks][1], aF[ks][2], aF[ks][3],
                  sptr(aslice + swz(arowL, ach)));
        }

        // ---- m16 x n512 x k64: branchless top-2 per row (r0, r1) ----
        float m1[2] = {CUDART_INF_F, CUDART_INF_F};
        float m2[2] = {CUDART_INF_F, CUDART_INF_F};
        int   ki[2] = {0x7FFFFFFF, 0x7FFFFFFF};

        #define UPD(rr, s, kk) {                                   \
            const bool lt = (s) < m1[rr];                          \
            m2[rr] = fminf(m2[rr], lt ? m1[rr] : (s));             \
            ki[rr] = lt ? (kk) : ki[rr];                           \
            m1[rr] = lt ? (s) : m1[rr]; }

        for (int nc = 0; nc < 8; nc++) {      // 8 chunks of 64 codes
            float acc[8][4];
            #pragma unroll
            for (int nf = 0; nf < 8; nf++) {
                acc[nf][0] = 0.f; acc[nf][1] = 0.f; acc[nf][2] = 0.f; acc[nf][3] = 0.f;
            }
            #pragma unroll
            for (int ks = 0; ks < 4; ks++) {
                uint32_t bh[8][2];
                #pragma unroll
                for (int pr = 0; pr < 4; pr++) {
                    const int row = nc * 64 + pr * 16 + browo;
                    const int ch  = 2 * ks + bchs;
                    LDSM4(bh[2 * pr][0], bh[2 * pr][1],
                          bh[2 * pr + 1][0], bh[2 * pr + 1][1],
                          sptr(sm + SM_B0 + swz(row, ch)));
                }
                #pragma unroll
                for (int nf = 0; nf < 8; nf++)
                    hmma(acc[nf][0], acc[nf][1], acc[nf][2], acc[nf][3],
                         aF[ks][0], aF[ks][1], aF[ks][2], aF[ks][3],
                         bh[nf][0], bh[nf][1]);
            }
            #pragma unroll
            for (int nf = 0; nf < 8; nf++) {
                const int col = nc * 64 + nf * 8 + 2 * g;
                const float2 eq = *reinterpret_cast<const float2*>(esq + col);
                float s;
                s = __fmaf_rn(-2.0f, acc[nf][0], eq.x); UPD(0, s, col);
                s = __fmaf_rn(-2.0f, acc[nf][1], eq.y); UPD(0, s, col + 1);
                s = __fmaf_rn(-2.0f, acc[nf][2], eq.x); UPD(1, s, col);
                s = __fmaf_rn(-2.0f, acc[nf][3], eq.y); UPD(1, s, col + 1);
            }
        }
        #undef UPD

        // ---- quad reduce (converged, full warp) ----
        #pragma unroll
        for (int rr = 0; rr < 2; rr++) {
            #pragma unroll
            for (int d = 1; d <= 2; d <<= 1) {
                const float o1 = __shfl_xor_sync(0xffffffffu, m1[rr], d);
                const float o2 = __shfl_xor_sync(0xffffffffu, m2[rr], d);
                const int   oi = __shfl_xor_sync(0xffffffffu, ki[rr], d);
                const bool take = (o1 < m1[rr]) || (o1 == m1[rr] && oi < ki[rr]);
                m2[rr] = fminf(fminf(m2[rr], o2), take ? m1[rr] : o1);
                ki[rr] = take ? oi : ki[rr];
                m1[rr] = take ? o1 : m1[rr];
            }
            if (g == 0) {
                const int row = qr + 8 * rr;
                scrWin[row] = (m2[rr] - m1[rr] > MARGIN) ? ki[rr] : -1;
            }
        }
        __syncwarp();

        // ---- in-warp exact rescue (warp-uniform control flow) ----
        #pragma unroll 1
        for (int r = 0; r < 16; r++) {
            if (scrWin[r] != -1) continue;          // LDS broadcast, uniform
            // load x row r (fp32) into scratch
            scrX[lane]      = __ldg(xb + (size_t)lane * VQ_HW + r);
            scrX[lane + 32] = __ldg(xb + (size_t)(lane + 32) * VQ_HW + r);
            __syncwarp();
            // sequential xsq (reference order), computed redundantly per lane
            float xq = 0.0f;
            #pragma unroll
            for (int c = 0; c < VQ_D; c++)
                xq = __fadd_rn(xq, __fmul_rn(scrX[c], scrX[c]));
            float bd = CUDART_INF_F; int bk = 0x7FFFFFFF;
            #pragma unroll 2
            for (int k = lane; k < VQ_K; k += 32) {
                const float d = exact_dist(scrX, emb, xq, esq[k], k);
                if (d < bd || (d == bd && k < bk)) { bd = d; bk = k; }
            }
            #pragma unroll
            for (int off = 16; off; off >>= 1) {
                const float od = __shfl_xor_sync(0xffffffffu, bd, off);
                const int   oi = __shfl_xor_sync(0xffffffffu, bk, off);
                if (od < bd || (od == bd && oi < bk)) { bd = od; bk = oi; }
            }
            if (lane == 0) scrWin[r] = bk;
            __syncwarp();
        }
        __syncwarp();

        // ---- gather winners + store (float4 along pixel dim) ----
        #pragma unroll
        for (int it = 0; it < 8; it++) {
            const int c  = it * 8 + (lane >> 2);
            const int p4 = (lane & 3) * 4;
            const int w0 = scrWin[p4 + 0], w1 = scrWin[p4 + 1];
            const int w2 = scrWin[p4 + 2], w3 = scrWin[p4 + 3];
            float4 v;
            v.x = __ldg(emb + (size_t)w0 * VQ_D + c);
            v.y = __ldg(emb + (size_t)w1 * VQ_D + c);
            v.z = __ldg(emb + (size_t)w2 * VQ_D + c);
            v.w = __ldg(emb + (size_t)w3 * VQ_D + c);
            *reinterpret_cast<float4*>(ob + (size_t)c * VQ_HW + p4) = v;
        }
    }
}

extern "C" void kernel_launch(void* const* d_in, const int* in_sizes, int n_in,
                              void* d_out, int out_size) {
    (void)in_sizes; (void)n_in; (void)out_size;
    const float* x   = (const float*)d_in[0];
    const float* emb = (const float*)d_in[1];
    float* out = (float*)d_out;

    cudaFuncSetAttribute(vq_hmma_kernel, cudaFuncAttributeMaxDynamicSharedMemorySize,
                         SMEM_TOTAL);

    vq_hmma_kernel<<<GRID, THREADS, SMEM_TOTAL>>>(x, emb, out);
}

// round 14
// speedup vs baseline: 2.7066x; 1.0255x over previous
#include <cuda_runtime.h>
#include <cuda_fp16.h>
#include <cstdint>
#include <math_constants.h>

// VectorQuantizer, barrier-free warp-autonomous version, 32 px/warp.
// R14 = R13 (126us, rel_err 0) with each warp owning TWO m16 A tiles that
// share every B fragment (register-blocked: n split into halves of 4 nf so
// acc stays <=128 regs). B LDSM traffic per pixel is halved -- L1 wavefronts
// were R13's binding resource (L1=60.8%).
// fp16 1-pass + MARGIN 6e-5 validated (rel_err 0.0 in R12/R13); exact fp32
// rescue formula bit-matched the reference in R1/R2.

#define VQ_K 512
#define VQ_D 64
#define VQ_HW 4096
#define NWTILES 4096         // 131072 px / 32 px per warp-tile
#define THREADS 512
#define NWARPS 16
#define GRID 152
#define MARGIN 6e-5f

// ---- shared memory layout (bytes) ----
#define SM_B0   0                       // codebook fp16 [512][128B]  64 KB
#define SM_ESQ  65536                   // f32 e_sq[512]               2 KB
#define SM_A    67584                   // per-warp A slices: 16 x 4096 = 64 KB
#define SM_SCR  133120                  // per-warp scratch: 16 x 512
#define SMEM_TOTAL 141312
// scratch per warp: f32 xrow[64] (256B) + int win[32] (128B) + pad

__device__ __forceinline__ int swz(int row, int chunk) {
    return row * 128 + ((chunk ^ (row & 7)) << 4);
}
__device__ __forceinline__ uint32_t sptr(const void* p) {
    return (uint32_t)__cvta_generic_to_shared(p);
}
#define LDSM4(r0, r1, r2, r3, addr)                                            \
    asm volatile("ldmatrix.sync.aligned.m8n8.x4.shared.b16 {%0,%1,%2,%3}, [%4];" \
                 : "=r"(r0), "=r"(r1), "=r"(r2), "=r"(r3) : "r"(addr))

__device__ __forceinline__ void hmma(float& d0, float& d1, float& d2, float& d3,
                                     uint32_t a0, uint32_t a1, uint32_t a2, uint32_t a3,
                                     uint32_t b0, uint32_t b1) {
    asm volatile(
        "mma.sync.aligned.m16n8k16.row.col.f32.f16.f16.f32 "
        "{%0,%1,%2,%3}, {%4,%5,%6,%7}, {%8,%9}, {%0,%1,%2,%3};"
        : "+f"(d0), "+f"(d1), "+f"(d2), "+f"(d3)
        : "r"(a0), "r"(a1), "r"(a2), "r"(a3), "r"(b0), "r"(b1));
}

__device__ __forceinline__ uint32_t pack2h(float a, float b) {
    __half2 h = __floats2half2_rn(a, b);
    return *reinterpret_cast<uint32_t*>(&h);
}

// Exact fp32 distance, numerics identical to round-1 (bit-matched reference):
// sequential FMA dot over channels, dist = fl(fl(xsq+esq) + (-2*dot)).
__device__ __forceinline__ float exact_dist(const float* __restrict__ xrow,
                                            const float* __restrict__ emb,
                                            float xsq, float esqk, int k) {
    const float4* er = reinterpret_cast<const float4*>(emb + (size_t)k * VQ_D);
    float dot = 0.0f;
    #pragma unroll
    for (int q = 0; q < 16; q++) {
        const float4 f = __ldg(er + q);
        dot = __fmaf_rn(xrow[4 * q + 0], f.x, dot);
        dot = __fmaf_rn(xrow[4 * q + 1], f.y, dot);
        dot = __fmaf_rn(xrow[4 * q + 2], f.z, dot);
        dot = __fmaf_rn(xrow[4 * q + 3], f.w, dot);
    }
    return __fadd_rn(__fadd_rn(xsq, esqk), __fmul_rn(-2.0f, dot));
}

__global__ __launch_bounds__(THREADS, 1)
void vq_hmma_kernel(const float* __restrict__ x,
                    const float* __restrict__ emb,
                    float* __restrict__ out) {
    extern __shared__ char sm[];
    float* esq = reinterpret_cast<float*>(sm + SM_ESQ);

    const int tid  = threadIdx.x;
    const int wid  = tid >> 5;
    const int lane = tid & 31;
    const int g    = lane & 3;
    const int qr   = lane >> 2;

    char*  aslice = sm + SM_A + wid * 4096;          // 2 tiles x 2048B
    float* scrX   = reinterpret_cast<float*>(sm + SM_SCR + wid * 512);
    int*   scrWin = reinterpret_cast<int*>(sm + SM_SCR + wid * 512 + 256);

    // ---- prologue: stage codebook fp16 (swizzled) + exact e_sq ----
    #pragma unroll 4
    for (int it = 0; it < 16; it++) {
        const int lin = it * THREADS + tid;          // 8192 float4s
        const int k = lin >> 4, q = lin & 15;
        const float4 f = __ldg(reinterpret_cast<const float4*>(emb + k * VQ_D) + q);
        const int off = swz(k, q >> 1) + (q & 1) * 8;
        *reinterpret_cast<uint2*>(sm + SM_B0 + off) =
            make_uint2(pack2h(f.x, f.y), pack2h(f.z, f.w));
    }
    {
        const int k = tid;                           // THREADS == VQ_K
        const float4* er = reinterpret_cast<const float4*>(emb + k * VQ_D);
        float s = 0.0f;
        #pragma unroll
        for (int q = 0; q < 16; q++) {
            const float4 f = __ldg(er + q);
            s = __fadd_rn(s, __fmul_rn(f.x, f.x));
            s = __fadd_rn(s, __fmul_rn(f.y, f.y));
            s = __fadd_rn(s, __fmul_rn(f.z, f.z));
            s = __fadd_rn(s, __fmul_rn(f.w, f.w));
        }
        esq[k] = s;
    }
    __syncthreads();   // only block barrier in the kernel

    const int browo = (lane & 7) + (lane >> 4) * 8;
    const int bchs  = (lane >> 3) & 1;
    const int arowL = (lane & 7) + ((lane >> 3) & 1) * 8;

    // warp-major tile interleave: balances 1-vs-2-tile warps across all SMs
    for (int wt = wid * GRID + blockIdx.x; wt < NWTILES; wt += GRID * NWARPS) {
        const int p0 = wt * 32;
        const int b  = p0 >> 12;
        const int hw = p0 & 4095;
        const float* xb = x + (size_t)b * VQ_D * VQ_HW + hw;
        float* ob = out + (size_t)b * VQ_D * VQ_HW + hw;

        __syncwarp();   // previous tile's LDSM fully done before slice rewrite

        // ---- stage 32 x-rows into two fp16 A tiles ----
        #pragma unroll
        for (int t = 0; t < 2; t++) {
            const float* xt = xb + 16 * t;
            char* at = aslice + 2048 * t;
            #pragma unroll
            for (int h = 0; h < 8; h++) {
                uint32_t pr[4];
                #pragma unroll
                for (int jj = 0; jj < 4; jj++) {
                    const int j = 4 * h + jj;
                    const int c = 2 * j + (lane >> 4);
                    const int p = lane & 15;
                    const float v = __ldg(xt + (size_t)c * VQ_HW + p);
                    const float o = __shfl_xor_sync(0xffffffffu, v, 16);
                    pr[jj] = pack2h(v, o);           // valid on lanes < 16
                }
                if (lane < 16) {
                    *reinterpret_cast<uint4*>(at + swz(lane, h)) =
                        make_uint4(pr[0], pr[1], pr[2], pr[3]);
                }
            }
        }
        __syncwarp();

        // ---- A fragments via ldmatrix.x4 (both tiles) ----
        uint32_t aF[2][4][4];
        #pragma unroll
        for (int t = 0; t < 2; t++) {
            #pragma unroll
            for (int ks = 0; ks < 4; ks++) {
                const int ach = 2 * ks + (lane >> 4);
                LDSM4(aF[t][ks][0], aF[t][ks][1], aF[t][ks][2], aF[t][ks][3],
                      sptr(aslice + 2048 * t + swz(arowL, ach)));
            }
        }

        // ---- m32 x n512 x k64: branchless top-2, 4 rows per thread ----
        float m1[4] = {CUDART_INF_F, CUDART_INF_F, CUDART_INF_F, CUDART_INF_F};
        float m2[4] = {CUDART_INF_F, CUDART_INF_F, CUDART_INF_F, CUDART_INF_F};
        int   ki[4] = {0x7FFFFFFF, 0x7FFFFFFF, 0x7FFFFFFF, 0x7FFFFFFF};

        #define UPD(rr, s, kk) {                                   \
            const bool lt = (s) < m1[rr];                          \
            m2[rr] = fminf(m2[rr], lt ? m1[rr] : (s));             \
            ki[rr] = lt ? (kk) : ki[rr];                           \
            m1[rr] = lt ? (s) : m1[rr]; }

        for (int nc = 0; nc < 8; nc++) {          // 8 chunks of 64 codes
            #pragma unroll
            for (int h = 0; h < 2; h++) {         // n-half: nf in [4h, 4h+4)
                float acc[2][4][4];
                #pragma unroll
                for (int t = 0; t < 2; t++)
                    #pragma unroll
                    for (int nfl = 0; nfl < 4; nfl++) {
                        acc[t][nfl][0] = 0.f; acc[t][nfl][1] = 0.f;
                        acc[t][nfl][2] = 0.f; acc[t][nfl][3] = 0.f;
                    }
                #pragma unroll
                for (int ks = 0; ks < 4; ks++) {
                    uint32_t bh[4][2];
                    #pragma unroll
                    for (int pr2 = 0; pr2 < 2; pr2++) {
                        const int pr = 2 * h + pr2;
                        const int row = nc * 64 + pr * 16 + browo;
                        const int ch  = 2 * ks + bchs;
                        LDSM4(bh[2 * pr2][0], bh[2 * pr2][1],
                              bh[2 * pr2 + 1][0], bh[2 * pr2 + 1][1],
                              sptr(sm + SM_B0 + swz(row, ch)));
                    }
                    #pragma unroll
                    for (int t = 0; t < 2; t++)
                        #pragma unroll
                        for (int nfl = 0; nfl < 4; nfl++)
                            hmma(acc[t][nfl][0], acc[t][nfl][1],
                                 acc[t][nfl][2], acc[t][nfl][3],
                                 aF[t][ks][0], aF[t][ks][1],
                                 aF[t][ks][2], aF[t][ks][3],
                                 bh[nfl][0], bh[nfl][1]);
                }
                // scores: rank = esq - 2*dot (xsq constant per row)
                #pragma unroll
                for (int t = 0; t < 2; t++)
                    #pragma unroll
                    for (int nfl = 0; nfl < 4; nfl++) {
                        const int col = nc * 64 + (4 * h + nfl) * 8 + 2 * g;
                        const float2 eq = *reinterpret_cast<const float2*>(esq + col);
                        float s;
                        s = __fmaf_rn(-2.0f, acc[t][nfl][0], eq.x); UPD(2 * t + 0, s, col);
                        s = __fmaf_rn(-2.0f, acc[t][nfl][1], eq.y); UPD(2 * t + 0, s, col + 1);
                        s = __fmaf_rn(-2.0f, acc[t][nfl][2], eq.x); UPD(2 * t + 1, s, col);
                        s = __fmaf_rn(-2.0f, acc[t][nfl][3], eq.y); UPD(2 * t + 1, s, col + 1);
                    }
            }
        }
        #undef UPD

        // ---- quad reduce (converged, full warp); write winner or -1 ----
        #pragma unroll
        for (int rr = 0; rr < 4; rr++) {
            #pragma unroll
            for (int d = 1; d <= 2; d <<= 1) {
                const float o1 = __shfl_xor_sync(0xffffffffu, m1[rr], d);
                const float o2 = __shfl_xor_sync(0xffffffffu, m2[rr], d);
                const int   oi = __shfl_xor_sync(0xffffffffu, ki[rr], d);
                const bool take = (o1 < m1[rr]) || (o1 == m1[rr] && oi < ki[rr]);
                m2[rr] = fminf(fminf(m2[rr], o2), take ? m1[rr] : o1);
                ki[rr] = take ? oi : ki[rr];
                m1[rr] = take ? o1 : m1[rr];
            }
            if (g == 0) {
                // rr = 2*t + sub: row = t*16 + qr + 8*sub
                const int row = (rr >> 1) * 16 + qr + 8 * (rr & 1);
                scrWin[row] = (m2[rr] - m1[rr] > MARGIN) ? ki[rr] : -1;
            }
        }
        __syncwarp();

        // ---- in-warp exact rescue (warp-uniform control flow) ----
        #pragma unroll 1
        for (int r = 0; r < 32; r++) {
            if (scrWin[r] != -1) continue;          // LDS broadcast, uniform
            scrX[lane]      = __ldg(xb + (size_t)lane * VQ_HW + r);
            scrX[lane + 32] = __ldg(xb + (size_t)(lane + 32) * VQ_HW + r);
            __syncwarp();
            float xq = 0.0f;
            #pragma unroll
            for (int c = 0; c < VQ_D; c++)
                xq = __fadd_rn(xq, __fmul_rn(scrX[c], scrX[c]));
            float bd = CUDART_INF_F; int bk = 0x7FFFFFFF;
            #pragma unroll 2
            for (int k = lane; k < VQ_K; k += 32) {
                const float d = exact_dist(scrX, emb, xq, esq[k], k);
                if (d < bd || (d == bd && k < bk)) { bd = d; bk = k; }
            }
            #pragma unroll
            for (int off = 16; off; off >>= 1) {
                const float od = __shfl_xor_sync(0xffffffffu, bd, off);
                const int   oi = __shfl_xor_sync(0xffffffffu, bk, off);
                if (od < bd || (od == bd && oi < bk)) { bd = od; bk = oi; }
            }
            if (lane == 0) scrWin[r] = bk;
            __syncwarp();
        }
        __syncwarp();

        // ---- gather winners + store (float4 along pixel dim), both halves ----
        #pragma unroll
        for (int t = 0; t < 2; t++) {
            #pragma unroll
            for (int it = 0; it < 8; it++) {
                const int c  = it * 8 + (lane >> 2);
                const int p4 = (lane & 3) * 4;
                const int w0 = scrWin[16 * t + p4 + 0], w1 = scrWin[16 * t + p4 + 1];
                const int w2 = scrWin[16 * t + p4 + 2], w3 = scrWin[16 * t + p4 + 3];
                float4 v;
                v.x = __ldg(emb + (size_t)w0 * VQ_D + c);
                v.y = __ldg(emb + (size_t)w1 * VQ_D + c);
                v.z = __ldg(emb + (size_t)w2 * VQ_D + c);
                v.w = __ldg(emb + (size_t)w3 * VQ_D + c);
                *reinterpret_cast<float4*>(ob + (size_t)c * VQ_HW + 16 * t + p4) = v;
            }
        }
    }
}

extern "C" void kernel_launch(void* const* d_in, const int* in_sizes, int n_in,
                              void* d_out, int out_size) {
    (void)in_sizes; (void)n_in; (void)out_size;
    const float* x   = (const float*)d_in[0];
    const float* emb = (const float*)d_in[1];
    float* out = (float*)d_out;

    cudaFuncSetAttribute(vq_hmma_kernel, cudaFuncAttributeMaxDynamicSharedMemorySize,
                         SMEM_TOTAL);

    vq_hmma_kernel<<<GRID, THREADS, SMEM_TOTAL>>>(x, emb, out);
}